// round 10
// baseline (speedup 1.0000x reference)
#include <cuda_runtime.h>
#include <math.h>
#include <stdint.h>

// VectorQuantizer: tf32 mma.sync (HMMA — portable PTX, assembles on plain
// sm_103 target, unlike tcgen05) screening + bit-exact rescreen of near-ties.
//
// Reference semantics (R6-proven bit-exact):
//   v_k = fl( fl(sumxx + cnorm_k) - 2*dot_k ), all three accumulated
//   sequentially over d=0..63 in fp32; argmin, first-min tie-break.
//
// Screen: s'_k = cnorm_k - 2*dot'_k with dot' from tf32 m16n8k8 mma
// (sumxx row-constant -> argmin-invariant). Rows with top-2 gap < MARGIN are
// rescreened exactly. tf32 score error ~2e-5 RMS + ref quantization 1.5e-5;
// MARGIN = 2.5e-4 (~10 sigma) flags ~5% of rows.

#define CD      64
#define HW      4096
#define NC      512
#define MTILE   128
#define THREADS 256
#define MARGIN  2.5e-4f

// ---- smem layout (bytes) ----
#define XS_STRIDE 65                        // fp32 X tile [128][65] (pad: conflict-free)
#define XS_OFF    0
#define SXX_OFF   (128 * XS_STRIDE * 4)     // 33280: float sxx[128]
#define CN_OFF    (SXX_OFF + 512)           // 33792: float cnorm[512]
#define B2_OFF    (CN_OFF + 2048)           // 35840: u64 b2[32][516] (tf32-pair packed)
#define B2_ROW    516                       // stride 516 (==4 mod 16 -> conflict-free LDS.64)
#define RG_OFF    (B2_OFF + 32 * B2_ROW * 8)  // 167936: float row_gap[8][16]
#define RB_OFF    (RG_OFF + 512)              // 168448: int row_bi[8][16]
#define SM_TOTAL  (RB_OFF + 512)              // 168960

extern __shared__ char smem[];

__device__ __forceinline__ uint32_t f2tf32(float f) {
    uint32_t r;
    asm("cvt.rna.tf32.f32 %0, %1;" : "=r"(r) : "f"(f));
    return r;
}
// D += A(16x8,row) * B(8x8,col), tf32 in / fp32 accum
__device__ __forceinline__ void mma_tf32(float* c, const uint32_t* a, uint32_t b0, uint32_t b1) {
    asm("mma.sync.aligned.m16n8k8.row.col.f32.tf32.tf32.f32 "
        "{%0,%1,%2,%3}, {%4,%5,%6,%7}, {%8,%9}, {%0,%1,%2,%3};"
        : "+f"(c[0]), "+f"(c[1]), "+f"(c[2]), "+f"(c[3])
        : "r"(a[0]), "r"(a[1]), "r"(a[2]), "r"(a[3]), "r"(b0), "r"(b1));
}

__global__ void __launch_bounds__(THREADS, 1) vq_kernel(
    const float* __restrict__ in, const float* __restrict__ cb, float* __restrict__ out)
{
    const int t   = threadIdx.x;
    const int wid = t >> 5, lid = t & 31;
    const int q   = lid >> 2, km = lid & 3;      // mma groupID / threadID-in-group

    float*    xs  = (float*)(smem + XS_OFF);
    float*    sxx = (float*)(smem + SXX_OFF);
    float*    cn  = (float*)(smem + CN_OFF);
    uint64_t* b2  = (uint64_t*)(smem + B2_OFF);
    float*    rg  = (float*)(smem + RG_OFF);
    int*      rb  = (int*)(smem + RB_OFF);

    const int m0   = blockIdx.x * MTILE;
    const int bimg = blockIdx.x >> 5;            // batch image (4096 % 128 == 0)
    const int pos0 = (blockIdx.x & 31) * MTILE;
    const float* xbase = in + (size_t)bimg * (CD * HW) + pos0;

    // ---- stage X tile fp32 (exact; feeds mma frags, sumxx, and rescreen) ----
    for (int i = t; i < MTILE * CD; i += THREADS) {
        const int d = i >> 7, m = i & 127;       // coalesced: consecutive t -> consecutive m
        xs[m * XS_STRIDE + d] = __ldg(xbase + d * HW + m);
    }
    // ---- stage codebook as packed tf32 pairs: word(s,km,n) = {c_n[8s+km], c_n[8s+km+4]} ----
    for (int i = t; i < NC * 32; i += THREADS) {
        const int n = i & 511, kk = i >> 9;      // kk = s*4 + km
        const int k0 = (kk >> 2) * 8 + (kk & 3);
        const uint64_t lo = f2tf32(__ldg(cb + n * CD + k0));
        const uint64_t hi = f2tf32(__ldg(cb + n * CD + k0 + 4));
        b2[(size_t)kk * B2_ROW + n] = lo | (hi << 32);
    }
    // ---- exact cnorm (sequential mul+add, R6 recipe) ----
    for (int k = t; k < NC; k += THREADS) {
        const float* cr = cb + (size_t)k * CD;
        float s = 0.f;
        #pragma unroll
        for (int d = 0; d < CD; d++) {
            float c = __ldg(cr + d);
            s = __fadd_rn(s, __fmul_rn(c, c));
        }
        cn[k] = s;
    }
    __syncthreads();

    // ---- exact sumxx per vector (sequential, from fp32 xs) ----
    if (t < MTILE) {
        const float* xr = xs + t * XS_STRIDE;
        float s = 0.f;
        #pragma unroll
        for (int d = 0; d < CD; d++) s = __fadd_rn(s, __fmul_rn(xr[d], xr[d]));
        sxx[t] = s;
    }

    // ---- A fragments (tf32), rows rw..rw+15, all 8 k-steps, kept in regs ----
    const int rw = wid * 16;
    uint32_t a[8][4];
    #pragma unroll
    for (int s = 0; s < 8; s++) {
        const int c0 = s * 8 + km;
        a[s][0] = f2tf32(xs[(rw + q) * XS_STRIDE + c0]);
        a[s][1] = f2tf32(xs[(rw + q + 8) * XS_STRIDE + c0]);
        a[s][2] = f2tf32(xs[(rw + q) * XS_STRIDE + c0 + 4]);
        a[s][3] = f2tf32(xs[(rw + q + 8) * XS_STRIDE + c0 + 4]);
    }
    __syncthreads();                             // publish sxx (b2/cn already synced)

    // ---- screen: 8 N-chunks of 64 codes; per-lane top-2 for rows rA=rw+q, rB=+8 ----
    float bA1 = INFINITY, bA2 = INFINITY, bB1 = INFINITY, bB2 = INFINITY;
    int   iA = 0, iB = 0;

    #pragma unroll 1
    for (int ch = 0; ch < 8; ch++) {
        const int n0 = ch * 64;
        float acc[8][4];
        #pragma unroll
        for (int nt = 0; nt < 8; nt++)
            #pragma unroll
            for (int c = 0; c < 4; c++) acc[nt][c] = 0.f;

        #pragma unroll
        for (int s = 0; s < 8; s++) {
            const uint64_t* brow = b2 + (size_t)(s * 4 + km) * B2_ROW + n0 + q;
            #pragma unroll
            for (int nt = 0; nt < 8; nt++) {     // conflict-free LDS.64
                const uint64_t w = brow[nt * 8];
                mma_tf32(acc[nt], a[s], (uint32_t)w, (uint32_t)(w >> 32));
            }
        }
        // epilogue: s' = cnorm - 2*dot ; per-lane k ascending -> strict '<' = first-min
        #pragma unroll
        for (int nt = 0; nt < 8; nt++) {
            const int kbase = n0 + nt * 8 + km * 2;
            #pragma unroll
            for (int c = 0; c < 2; c++) {
                const int k = kbase + c;
                float v = fmaf(-2.f, acc[nt][c], cn[k]);
                if (v < bA1) { bA2 = bA1; bA1 = v; iA = k; } else bA2 = fminf(bA2, v);
                v = fmaf(-2.f, acc[nt][c + 2], cn[k]);
                if (v < bB1) { bB2 = bB1; bB1 = v; iB = k; } else bB2 = fminf(bB2, v);
            }
        }
    }

    // ---- reduce top-2 across the 4 lanes sharing each row (xor 1, then 2) ----
    #pragma unroll
    for (int o = 1; o <= 2; o <<= 1) {
        float cA1 = __shfl_xor_sync(0xffffffffu, bA1, o);
        float cA2 = __shfl_xor_sync(0xffffffffu, bA2, o);
        int   jA  = __shfl_xor_sync(0xffffffffu, iA,  o);
        if (cA1 < bA1 || (cA1 == bA1 && jA < iA)) { bA2 = fminf(bA1, cA2); bA1 = cA1; iA = jA; }
        else                                      { bA2 = fminf(bA2, cA1); }
        float cB1 = __shfl_xor_sync(0xffffffffu, bB1, o);
        float cB2 = __shfl_xor_sync(0xffffffffu, bB2, o);
        int   jB  = __shfl_xor_sync(0xffffffffu, iB,  o);
        if (cB1 < bB1 || (cB1 == bB1 && jB < iB)) { bB2 = fminf(bB1, cB2); bB1 = cB1; iB = jB; }
        else                                      { bB2 = fminf(bB2, cB1); }
    }
    if (km == 0) {                               // lane holds rows q and q+8
        rg[wid * 16 + q]     = bA2 - bA1;  rb[wid * 16 + q]     = iA;
        rg[wid * 16 + q + 8] = bB2 - bB1;  rb[wid * 16 + q + 8] = iB;
    }
    __syncwarp();

    // ---- rescreen flagged rows: bit-exact R6 recipe, warp-cooperative ----
    for (int r = 0; r < 16; r++) {
        if (rg[wid * 16 + r] >= MARGIN) continue;
        const float sx = sxx[rw + r];
        const float* xr = xs + (rw + r) * XS_STRIDE;   // broadcast LDS
        float bv = INFINITY; int bk = 0;
        for (int kk = 0; kk < 16; kk++) {              // lane: codes 16*lid.. ascending
            const int k = lid * 16 + kk;
            const float* cr = cb + (size_t)k * CD;
            float dot = 0.f;
            #pragma unroll
            for (int d = 0; d < CD; d++)               // exact: sequential-d FMA
                dot = __fmaf_rn(xr[d], __ldg(cr + d), dot);
            const float v = __fsub_rn(__fadd_rn(sx, cn[k]), __fmul_rn(2.f, dot));
            if (v < bv) { bv = v; bk = k; }
        }
        #pragma unroll
        for (int o = 16; o; o >>= 1) {                 // lexicographic (v,k) min
            const float ov = __shfl_down_sync(0xffffffffu, bv, o);
            const int   ok = __shfl_down_sync(0xffffffffu, bk, o);
            if (ov < bv || (ov == bv && ok < bk)) { bv = ov; bk = ok; }
        }
        const int win = __shfl_sync(0xffffffffu, bk, 0);
        if (lid == 0) rb[wid * 16 + r] = win;
        __syncwarp();
    }

    // ---- write winners: warp copies its 16 rows (lane -> float2 slot) ----
    for (int r = 0; r < 16; r++) {
        const int bi = rb[wid * 16 + r];
        const float2 v = __ldg((const float2*)(cb + (size_t)bi * CD) + lid);
        ((float2*)(out + (size_t)(m0 + rw + r) * CD))[lid] = v;
    }
}

extern "C" void kernel_launch(void* const* d_in, const int* in_sizes, int n_in,
                              void* d_out, int out_size)
{
    const float* in = (const float*)d_in[0];   // (16,64,64,64) fp32
    const float* cb = (const float*)d_in[1];   // (512,64) fp32
    float* out = (float*)d_out;

    cudaFuncSetAttribute(vq_kernel, cudaFuncAttributeMaxDynamicSharedMemorySize, SM_TOTAL);
    vq_kernel<<<65536 / MTILE, THREADS, SM_TOTAL>>>(in, cb, out);
}

// round 12
// speedup vs baseline: 6.0897x; 6.0897x over previous
#include <cuda_runtime.h>
#include <math.h>

// VectorQuantizer: inputs (16,64,64,64) fp32 (b,c,h,w), codebook (512,64) fp32.
// Bit-exact replication of the reference's fp32 argmin (R6/R8: rel_err == 0.0):
//   v_k = fl( fl(sumxx + cnorm_k) - 2*dot_k ), dot/sumxx/cnorm accumulated
//   sequentially over d=0..63 with FMA; argmin, first-min tie-break.
// R11: grid reshaped 128x512thr -> 147x224thr (448 vec/CTA, V=2) so 147/148
// SMs are busy (R8 left 20 SMs idle). Same balanced FFMA2/LDS.128 main loop.

#define CD      64
#define HW      4096
#define NVEC    65536
#define NCODES  512
#define THREADS 224
#define VPT     (THREADS * 2)          // 448 vectors per CTA (V=2)
#define NTILES  ((NVEC + VPT - 1) / VPT)   // 147

typedef unsigned long long u64;

// d = a*b + c (packed fp32x2); lanes = two CODES, per-code accumulation
// strictly sequential in d (reference rounding order).
__device__ __forceinline__ u64 ffma2(u64 a, u64 b, u64 c) {
    u64 d;
    asm("fma.rn.f32x2 %0, %1, %2, %3;" : "=l"(d) : "l"(a), "l"(b), "l"(c));
    return d;
}
__device__ __forceinline__ u64 pack2(float lo, float hi) {
    u64 d;
    asm("mov.b64 %0, {%1, %2};" : "=l"(d) : "f"(lo), "f"(hi));
    return d;
}
__device__ __forceinline__ void unpack2(u64 v, float& lo, float& hi) {
    asm("mov.b64 {%0, %1}, %2;" : "=f"(lo), "=f"(hi) : "l"(v));
}

extern __shared__ float smem[];   // cbT[64][512] transposed codebook, then cnorm[512]

__global__ void __launch_bounds__(THREADS, 1) vq_kernel(
    const float* __restrict__ in, const float* __restrict__ cb, float* __restrict__ out)
{
    const int t = threadIdx.x;
    float* cbT   = smem;                  // cbT[d*512 + k]
    float* cnorm = smem + CD * NCODES;    // cnorm[k]

    // ---- Stage codebook transposed (rows k = t, t+224, ...) ----
    for (int k = t; k < NCODES; k += THREADS) {
        const float4* src = (const float4*)(cb + (size_t)k * CD);   // coalesced
        #pragma unroll
        for (int j = 0; j < 16; j++) {
            float4 v = src[j];
            cbT[(4 * j + 0) * NCODES + k] = v.x;   // consecutive k per lane
            cbT[(4 * j + 1) * NCODES + k] = v.y;
            cbT[(4 * j + 2) * NCODES + k] = v.z;
            cbT[(4 * j + 3) * NCODES + k] = v.w;
        }
    }
    __syncthreads();

    // ---- cnorm_k = sum(c^2), sequential mul+add (exact per R6 recipe) ----
    for (int k = t; k < NCODES; k += THREADS) {
        float s = 0.f;
        #pragma unroll
        for (int d = 0; d < CD; d++) {
            float c = cbT[d * NCODES + k];
            s = __fadd_rn(s, __fmul_rn(c, c));
        }
        cnorm[k] = s;
    }
    __syncthreads();

    // ---- Two x vectors per thread (guarded; tiles may be ragged/cross images) ----
    const int m0 = blockIdx.x * VPT;
    const int mA = m0 + t;
    const int mB = mA + THREADS;
    const bool vA = mA < NVEC, vB = mB < NVEC;
    const int mAc = vA ? mA : NVEC - 1;
    const int mBc = vB ? mB : NVEC - 1;
    const float* xpA = in + (size_t)(mAc >> 12) * (CD * HW) + (mAc & (HW - 1));
    const float* xpB = in + (size_t)(mBc >> 12) * (CD * HW) + (mBc & (HW - 1));

    float xa[CD], xb[CD];
    float sxa = 0.f, sxb = 0.f;
    #pragma unroll
    for (int d = 0; d < CD; d++) {
        xa[d] = __ldg(xpA + d * HW);               // coalesced across warp
        xb[d] = __ldg(xpB + d * HW);
        sxa = __fadd_rn(sxa, __fmul_rn(xa[d], xa[d]));
        sxb = __fadd_rn(sxb, __fmul_rn(xb[d], xb[d]));
    }

    // ---- Main loop: 16 codes/tile; each LDS.128 (broadcast) feeds BOTH vectors ----
    float bestA = INFINITY, bestB = INFINITY;
    int   biA   = 0,        biB   = 0;

    for (int k0 = 0; k0 < NCODES; k0 += 16) {
        u64 aA[8], aB[8];
        #pragma unroll
        for (int q = 0; q < 8; q++) { aA[q] = 0ull; aB[q] = 0ull; }

        #pragma unroll
        for (int d = 0; d < CD; d++) {
            u64 x2a = pack2(xa[d], xa[d]);
            u64 x2b = pack2(xb[d], xb[d]);
            const ulonglong2* row = (const ulonglong2*)(cbT + d * NCODES + k0);
            #pragma unroll
            for (int r = 0; r < 4; r++) {          // LDS.128: 4 codes at this d
                ulonglong2 c4 = row[r];
                aA[2 * r]     = ffma2(x2a, c4.x, aA[2 * r]);
                aA[2 * r + 1] = ffma2(x2a, c4.y, aA[2 * r + 1]);
                aB[2 * r]     = ffma2(x2b, c4.x, aB[2 * r]);
                aB[2 * r + 1] = ffma2(x2b, c4.y, aB[2 * r + 1]);
            }
        }

        // Epilogue: reference-exact  v = fl( fl(sumxx + cnorm) - 2*dot ),
        // ascending k, strict '<' => first-min tie-break.
        #pragma unroll
        for (int r = 0; r < 4; r++) {
            const int k = k0 + 4 * r;
            float a0, a1, a2, a3, b0, b1, b2, b3;
            unpack2(aA[2 * r],     a0, a1);
            unpack2(aA[2 * r + 1], a2, a3);
            unpack2(aB[2 * r],     b0, b1);
            unpack2(aB[2 * r + 1], b2, b3);
            float v;
            v = __fsub_rn(__fadd_rn(sxa, cnorm[k + 0]), __fmul_rn(2.f, a0));
            if (v < bestA) { bestA = v; biA = k + 0; }
            v = __fsub_rn(__fadd_rn(sxa, cnorm[k + 1]), __fmul_rn(2.f, a1));
            if (v < bestA) { bestA = v; biA = k + 1; }
            v = __fsub_rn(__fadd_rn(sxa, cnorm[k + 2]), __fmul_rn(2.f, a2));
            if (v < bestA) { bestA = v; biA = k + 2; }
            v = __fsub_rn(__fadd_rn(sxa, cnorm[k + 3]), __fmul_rn(2.f, a3));
            if (v < bestA) { bestA = v; biA = k + 3; }

            v = __fsub_rn(__fadd_rn(sxb, cnorm[k + 0]), __fmul_rn(2.f, b0));
            if (v < bestB) { bestB = v; biB = k + 0; }
            v = __fsub_rn(__fadd_rn(sxb, cnorm[k + 1]), __fmul_rn(2.f, b1));
            if (v < bestB) { bestB = v; biB = k + 1; }
            v = __fsub_rn(__fadd_rn(sxb, cnorm[k + 2]), __fmul_rn(2.f, b2));
            if (v < bestB) { bestB = v; biB = k + 2; }
            v = __fsub_rn(__fadd_rn(sxb, cnorm[k + 3]), __fmul_rn(2.f, b3));
            if (v < bestB) { bestB = v; biB = k + 3; }
        }
    }

    // ---- Write winning codebook rows (L2-hot gather), guarded ----
    if (vA) {
        const float4* srcA = (const float4*)(cb + (size_t)biA * CD);
        float4* dstA = (float4*)(out + (size_t)mA * CD);
        #pragma unroll
        for (int j = 0; j < 16; j++) dstA[j] = __ldg(srcA + j);
    }
    if (vB) {
        const float4* srcB = (const float4*)(cb + (size_t)biB * CD);
        float4* dstB = (float4*)(out + (size_t)mB * CD);
        #pragma unroll
        for (int j = 0; j < 16; j++) dstB[j] = __ldg(srcB + j);
    }
}

extern "C" void kernel_launch(void* const* d_in, const int* in_sizes, int n_in,
                              void* d_out, int out_size)
{
    const float* in = (const float*)d_in[0];   // inputs (16,64,64,64) fp32
    const float* cb = (const float*)d_in[1];   // codebook (512,64) fp32
    float* out = (float*)d_out;

    const int smem_bytes = (CD * NCODES + NCODES) * sizeof(float);  // 130 KB + 2 KB
    cudaFuncSetAttribute(vq_kernel, cudaFuncAttributeMaxDynamicSharedMemorySize, smem_bytes);
    vq_kernel<<<NTILES, THREADS, smem_bytes>>>(in, cb, out);
}